// round 12
// baseline (speedup 1.0000x reference)
#include <cuda_runtime.h>

// StoutSmearSlice: 24^4 lattice, 4 dirs, 3x3 complex links (separate re/im fp32).
// MU=0, update EVEN parity sites of dir 0; everything else is a copy.
//
// Round 12 = R11 (66.3us: evict-first stores + 9-term Taylor) with ONE change:
// __launch_bounds__(128, 6) caps regs at 85 (ptxas trims 94 -> ~84, ~10 regs of
// rematerialization, no spill expected) -> 6 blocks/SM instead of 5.

#define IDX9(d,t,z,y,x) ((((((d)*24+(t))*24+(z))*24+(y))*24+(x))*9)

static const int NSITE  = 24 * 24 * 24 * 12;          // even sites = 165888
static const int NCB    = NSITE / 128;                // 1296 compute blocks
static const int DIR_F  = 24 * 24 * 24 * 24 * 9;      // floats per direction
static const int COPY4  = 3 * DIR_F / 4;              // float4s in dirs 1..3
static const int PER_B  = 128 * 4;                    // float4s per copy block
static const int NCPB   = COPY4 / PER_B;              // 4374 dirs1-3 copy blocks
static const int NODD_E = NSITE * 9;                  // odd dir0 complex elements
static const int NODDB  = NODD_E / (128 * 4);         // 2916 odd-copy blocks

typedef unsigned long long c64;   // packed {lo=re, hi=im} fp32 pair

__device__ __forceinline__ c64 pk(float lo, float hi) {
    c64 r; asm("mov.b64 %0,{%1,%2};" : "=l"(r) : "f"(lo), "f"(hi)); return r;
}
__device__ __forceinline__ void upk(c64 v, float &lo, float &hi) {
    asm("mov.b64 {%0,%1},%2;" : "=f"(lo), "=f"(hi) : "l"(v));
}
__device__ __forceinline__ c64 fma2(c64 a, c64 b, c64 c) {
    c64 d; asm("fma.rn.f32x2 %0,%1,%2,%3;" : "=l"(d) : "l"(a), "l"(b), "l"(c));
    return d;
}
__device__ __forceinline__ c64 mul2(c64 a, c64 b) {
    c64 d; asm("mul.rn.f32x2 %0,%1,%2;" : "=l"(d) : "l"(a), "l"(b)); return d;
}

struct C3 { c64 m[9]; };

// Windowed load: base b is 4B-aligned; a = b&~1 is 8B-aligned and [a, a+10)
// covers elements [b, b+9). 5 LDG.64 per array + select.
__device__ __forceinline__ void mload(C3 &A, const float* __restrict__ re,
                                      const float* __restrict__ im, int b) {
    int a = b & ~1;
    bool p = (b & 1) != 0;
    const float2* r2 = (const float2*)(re + a);
    const float2* i2 = (const float2*)(im + a);
    float fr[10], fi[10];
#pragma unroll
    for (int j = 0; j < 5; j++) {
        float2 vr = r2[j], vi = i2[j];
        fr[2*j] = vr.x; fr[2*j+1] = vr.y;
        fi[2*j] = vi.x; fi[2*j+1] = vi.y;
    }
#pragma unroll
    for (int i = 0; i < 9; i++)
        A.m[i] = pk(p ? fr[i+1] : fr[i], p ? fi[i+1] : fi[i]);
}

// MODE: 0 = A@B, 1 = A@B^dag, 2 = A^dag@B
template <int MODE>
__device__ __forceinline__ void cmul(C3 &C, const C3 &A, const C3 &B) {
#pragma unroll
    for (int r = 0; r < 3; r++) {
        float ar[3], ai[3];
#pragma unroll
        for (int k = 0; k < 3; k++)
            upk(A.m[MODE == 2 ? k * 3 + r : r * 3 + k], ar[k], ai[k]);
        c64 arr[3], aii[3];
#pragma unroll
        for (int k = 0; k < 3; k++) { arr[k] = pk(ar[k], ar[k]); aii[k] = pk(ai[k], ai[k]); }
#pragma unroll
        for (int c = 0; c < 3; c++) {
            c64 b0 = B.m[MODE == 1 ? c * 3 + 0 : 0 * 3 + c];
            c64 acc1 = mul2(arr[0], b0);
            c64 acc2 = mul2(aii[0], b0);
#pragma unroll
            for (int k = 1; k < 3; k++) {
                c64 b = B.m[MODE == 1 ? c * 3 + k : k * 3 + c];
                acc1 = fma2(arr[k], b, acc1);
                acc2 = fma2(aii[k], b, acc2);
            }
            float x1, y1, x2, y2;
            upk(acc1, x1, y1); upk(acc2, x2, y2);
            float cr, ci;
            if (MODE == 0)      { cr = x1 - y2; ci = y1 + x2; }
            else if (MODE == 1) { cr = x1 + y2; ci = x2 - y1; }
            else                { cr = x1 + y2; ci = y1 - x2; }
            C.m[r * 3 + c] = pk(cr, ci);
        }
    }
}

__device__ __forceinline__ void macc(C3 &F, const C3 &T, float c) {
    c64 cc = pk(c, c);
#pragma unroll
    for (int i = 0; i < 9; i++) F.m[i] = fma2(cc, T.m[i], F.m[i]);
}

// Forward staple (cf) + backward staple (cb) for one nu direction.
__device__ __forceinline__ void staple_pair(C3 &f,
        const float* __restrict__ xre, const float* __restrict__ xim,
        int b0p, int b0m, int bns, int bnsmu, int bnm, int bnmmu,
        float cf, float cb) {
    C3 A, B, C, T1, T2;
    mload(A, xre, xim, b0p);        // U0(s+nu)
    mload(B, xre, xim, bnsmu);      // Unu(s+mu)
    cmul<1>(T1, A, B);              // U0(s+nu) @ Unu(s+mu)^dag
    mload(C, xre, xim, bns);        // Unu(s)
    cmul<0>(T2, C, T1);
    macc(f, T2, cf);

    mload(A, xre, xim, bnm);        // Unu(s-nu)
    mload(B, xre, xim, b0m);        // U0(s-nu)
    cmul<2>(T1, A, B);              // Unu(s-nu)^dag @ U0(s-nu)
    mload(C, xre, xim, bnmmu);      // Unu(s-nu+mu)
    cmul<0>(T2, T1, C);
    macc(f, T2, cb);
}

__global__ __launch_bounds__(128, 6) void stout_fused(
        const float* __restrict__ xre,
        const float* __restrict__ xim,
        const float* __restrict__ coeff,
        float2* __restrict__ out) {
    if (blockIdx.x >= NCB) {
        int rb = blockIdx.x - NCB;
        if (rb < NCPB) {
            // ---- copy role: dirs 1..3, float4 interleave ----
            const float4* re4 = (const float4*)(xre + DIR_F);
            const float4* im4 = (const float4*)(xim + DIR_F);
            float4* o4 = (float4*)(out + DIR_F);
            int base = rb * PER_B + threadIdx.x;
#pragma unroll
            for (int k = 0; k < 4; k++) {
                int i = base + k * 128;
                float4 r = re4[i], m = im4[i];
                __stcs(&o4[2*i],     make_float4(r.x, m.x, r.y, m.y));
                __stcs(&o4[2*i + 1], make_float4(r.z, m.z, r.w, m.w));
            }
        } else {
            // ---- odd-site dir-0 copy role ----
            int base = (rb - NCPB) * (128 * 4) + threadIdx.x;
#pragma unroll
            for (int k = 0; k < 4; k++) {
                int w = base + k * 128;          // odd-element linear index
                int s = w / 9, i = w - 9 * s;    // odd-site index, element
                int xi = s % 12; int r = s / 12;
                int y = r % 24; r /= 24;
                int z = r % 24; r /= 24;
                int t = r;
                int x = 2 * xi + (((t + z + y) & 1) ^ 1);   // odd parity
                int addr = IDX9(0, t, z, y, x) + i;
                __stcs(&out[addr], make_float2(xre[addr], xim[addr]));
            }
        }
        return;
    }

    // ---- compute role: one even site ----
    int tid = blockIdx.x * 128 + threadIdx.x;
    int xi = tid % 12; int r = tid / 12;
    int y = r % 24; r /= 24;
    int z = r % 24; r /= 24;
    int t = r;
    int x = 2 * xi + ((t + z + y) & 1);      // (t+z+y+x) even

    int tp = (t + 1) % 24;
    int zp = (z + 1) % 24, zm = (z + 23) % 24;
    int yp = (y + 1) % 24, ym = (y + 23) % 24;
    int xp = (x + 1) % 24, xm = (x + 23) % 24;

    // scale_coeff(coeff,0.75) with the /6 staple average folded in
    float c[6];
#pragma unroll
    for (int i = 0; i < 6; i++)
        c[i] = (0.47746482927568606f / 6.0f) * atanf(coeff[i]);

    C3 f;
#pragma unroll
    for (int i = 0; i < 9; i++) f.m[i] = 0ull;

    staple_pair(f, xre, xim,                     // nu = 1 (Z)
                IDX9(0,t,zp,y,x), IDX9(0,t,zm,y,x),
                IDX9(1,t,z,y,x),  IDX9(1,tp,z,y,x),
                IDX9(1,t,zm,y,x), IDX9(1,tp,zm,y,x),
                c[0], c[1]);
    staple_pair(f, xre, xim,                     // nu = 2 (Y)
                IDX9(0,t,z,yp,x), IDX9(0,t,z,ym,x),
                IDX9(2,t,z,y,x),  IDX9(2,tp,z,y,x),
                IDX9(2,t,z,ym,x), IDX9(2,tp,z,ym,x),
                c[2], c[3]);
    staple_pair(f, xre, xim,                     // nu = 3 (X)
                IDX9(0,t,z,y,xp), IDX9(0,t,z,y,xm),
                IDX9(3,t,z,y,x),  IDX9(3,tp,z,y,x),
                IDX9(3,t,z,y,xm), IDX9(3,tp,z,y,xm),
                c[4], c[5]);

    int b0 = IDX9(0, t, z, y, x);
    C3 U0; mload(U0, xre, xim, b0);

    // Z = projectTangent(f @ U0^dag) scaled by 2^-4
    C3 Mm; cmul<1>(Mm, f, U0);
    float mr[9], mi[9];
#pragma unroll
    for (int i = 0; i < 9; i++) upk(Mm.m[i], mr[i], mi[i]);
    const float s = 0.03125f;   // 0.5 * 2^-4
    float zre[9], zim[9];
#pragma unroll
    for (int rr = 0; rr < 3; rr++)
#pragma unroll
        for (int cc = 0; cc < 3; cc++) {
            zre[rr*3+cc] = s * (mr[rr*3+cc] - mr[cc*3+rr]);
            zim[rr*3+cc] = s * (mi[rr*3+cc] + mi[cc*3+rr]);
        }
    float tri = (zim[0] + zim[4] + zim[8]) * (1.0f / 3.0f);
    zim[0] -= tri; zim[4] -= tri; zim[8] -= tri;
    C3 Z;
#pragma unroll
    for (int i = 0; i < 9; i++) Z.m[i] = pk(zre[i], zim[i]);

    // Horner Taylor, 9 terms: E = I + (Z@E)/k
    const c64 one = pk(1.0f, 0.0f);
    C3 E, T1;
#pragma unroll
    for (int i = 0; i < 9; i++) E.m[i] = (i % 4 == 0) ? one : 0ull;
#pragma unroll
    for (int k = 9; k >= 1; k--) {
        cmul<0>(T1, Z, E);
        float inv = 1.0f / (float)k;
        c64 inv2 = pk(inv, inv);
#pragma unroll
        for (int i = 0; i < 9; i++)
            E.m[i] = fma2(T1.m[i], inv2, (i % 4 == 0) ? one : 0ull);
    }
    // 4 squarings
#pragma unroll
    for (int sq = 0; sq < 4; sq++) { cmul<0>(T1, E, E); E = T1; }

    // y_mu = E @ U0 (even sites: xmu_fix = 0)
    C3 Y; cmul<0>(Y, E, U0);
    double* outd = (double*)out;
#pragma unroll
    for (int i = 0; i < 9; i++)
        __stcs(&outd[b0 + i], __longlong_as_double((long long)Y.m[i]));
}

extern "C" void kernel_launch(void* const* d_in, const int* in_sizes, int n_in,
                              void* d_out, int out_size) {
    const float* xre   = (const float*)d_in[0];
    const float* xim   = (const float*)d_in[1];
    const float* coeff = (const float*)d_in[2];

    stout_fused<<<NCB + NCPB + NODDB, 128>>>(xre, xim, coeff, (float2*)d_out);
}

// round 14
// speedup vs baseline: 1.0633x; 1.0633x over previous
#include <cuda_runtime.h>

// StoutSmearSlice: 24^4 lattice, 4 dirs, 3x3 complex links (separate re/im fp32).
// MU=0, update EVEN parity sites of dir 0; everything else is a copy.
//
// Round 14 = resubmit of R13 (infra failure, no bench data).
// R13 = R11 (66.3us) + two traffic cuts:
//  - odd-copy role ELIMINATED: the compute thread's nu=3 staple already loads
//    the odd partner's U0 matrix (U0(s+x) if par==0 else U0(s-x)); store it
//    with 9 predicated stcs right after load. 2916 gather-read blocks vanish.
//  - Taylor 9 -> 8 terms (12->9 left rel_err bit-identical => ||Z||<~0.9;
//    8-term worst-case error ~1.6e-5 vs 1e-3 threshold).

#define IDX9(d,t,z,y,x) ((((((d)*24+(t))*24+(z))*24+(y))*24+(x))*9)

static const int NSITE  = 24 * 24 * 24 * 12;          // even sites = 165888
static const int NCB    = NSITE / 128;                // 1296 compute blocks
static const int DIR_F  = 24 * 24 * 24 * 24 * 9;      // floats per direction
static const int COPY4  = 3 * DIR_F / 4;              // float4s in dirs 1..3
static const int PER_B  = 128 * 4;                    // float4s per copy block
static const int NCPB   = COPY4 / PER_B;              // 4374 dirs1-3 copy blocks

typedef unsigned long long c64;   // packed {lo=re, hi=im} fp32 pair

__device__ __forceinline__ c64 pk(float lo, float hi) {
    c64 r; asm("mov.b64 %0,{%1,%2};" : "=l"(r) : "f"(lo), "f"(hi)); return r;
}
__device__ __forceinline__ void upk(c64 v, float &lo, float &hi) {
    asm("mov.b64 {%0,%1},%2;" : "=f"(lo), "=f"(hi) : "l"(v));
}
__device__ __forceinline__ c64 fma2(c64 a, c64 b, c64 c) {
    c64 d; asm("fma.rn.f32x2 %0,%1,%2,%3;" : "=l"(d) : "l"(a), "l"(b), "l"(c));
    return d;
}
__device__ __forceinline__ c64 mul2(c64 a, c64 b) {
    c64 d; asm("mul.rn.f32x2 %0,%1,%2;" : "=l"(d) : "l"(a), "l"(b)); return d;
}

struct C3 { c64 m[9]; };

// Windowed load: base b is 4B-aligned; a = b&~1 is 8B-aligned and [a, a+10)
// covers elements [b, b+9). 5 LDG.64 per array + select.
__device__ __forceinline__ void mload(C3 &A, const float* __restrict__ re,
                                      const float* __restrict__ im, int b) {
    int a = b & ~1;
    bool p = (b & 1) != 0;
    const float2* r2 = (const float2*)(re + a);
    const float2* i2 = (const float2*)(im + a);
    float fr[10], fi[10];
#pragma unroll
    for (int j = 0; j < 5; j++) {
        float2 vr = r2[j], vi = i2[j];
        fr[2*j] = vr.x; fr[2*j+1] = vr.y;
        fi[2*j] = vi.x; fi[2*j+1] = vi.y;
    }
#pragma unroll
    for (int i = 0; i < 9; i++)
        A.m[i] = pk(p ? fr[i+1] : fr[i], p ? fi[i+1] : fi[i]);
}

// MODE: 0 = A@B, 1 = A@B^dag, 2 = A^dag@B
template <int MODE>
__device__ __forceinline__ void cmul(C3 &C, const C3 &A, const C3 &B) {
#pragma unroll
    for (int r = 0; r < 3; r++) {
        float ar[3], ai[3];
#pragma unroll
        for (int k = 0; k < 3; k++)
            upk(A.m[MODE == 2 ? k * 3 + r : r * 3 + k], ar[k], ai[k]);
        c64 arr[3], aii[3];
#pragma unroll
        for (int k = 0; k < 3; k++) { arr[k] = pk(ar[k], ar[k]); aii[k] = pk(ai[k], ai[k]); }
#pragma unroll
        for (int c = 0; c < 3; c++) {
            c64 b0 = B.m[MODE == 1 ? c * 3 + 0 : 0 * 3 + c];
            c64 acc1 = mul2(arr[0], b0);
            c64 acc2 = mul2(aii[0], b0);
#pragma unroll
            for (int k = 1; k < 3; k++) {
                c64 b = B.m[MODE == 1 ? c * 3 + k : k * 3 + c];
                acc1 = fma2(arr[k], b, acc1);
                acc2 = fma2(aii[k], b, acc2);
            }
            float x1, y1, x2, y2;
            upk(acc1, x1, y1); upk(acc2, x2, y2);
            float cr, ci;
            if (MODE == 0)      { cr = x1 - y2; ci = y1 + x2; }
            else if (MODE == 1) { cr = x1 + y2; ci = x2 - y1; }
            else                { cr = x1 + y2; ci = y1 - x2; }
            C.m[r * 3 + c] = pk(cr, ci);
        }
    }
}

__device__ __forceinline__ void macc(C3 &F, const C3 &T, float c) {
    c64 cc = pk(c, c);
#pragma unroll
    for (int i = 0; i < 9; i++) F.m[i] = fma2(cc, T.m[i], F.m[i]);
}

// Forward staple (cf) + backward staple (cb) for one nu direction.
__device__ __forceinline__ void staple_pair(C3 &f,
        const float* __restrict__ xre, const float* __restrict__ xim,
        int b0p, int b0m, int bns, int bnsmu, int bnm, int bnmmu,
        float cf, float cb) {
    C3 A, B, C, T1, T2;
    mload(A, xre, xim, b0p);        // U0(s+nu)
    mload(B, xre, xim, bnsmu);      // Unu(s+mu)
    cmul<1>(T1, A, B);              // U0(s+nu) @ Unu(s+mu)^dag
    mload(C, xre, xim, bns);        // Unu(s)
    cmul<0>(T2, C, T1);
    macc(f, T2, cf);

    mload(A, xre, xim, bnm);        // Unu(s-nu)
    mload(B, xre, xim, b0m);        // U0(s-nu)
    cmul<2>(T1, A, B);              // Unu(s-nu)^dag @ U0(s-nu)
    mload(C, xre, xim, bnmmu);      // Unu(s-nu+mu)
    cmul<0>(T2, T1, C);
    macc(f, T2, cb);
}

__global__ __launch_bounds__(128) void stout_fused(
        const float* __restrict__ xre,
        const float* __restrict__ xim,
        const float* __restrict__ coeff,
        float2* __restrict__ out) {
    if (blockIdx.x >= NCB) {
        // ---- copy role: dirs 1..3, float4 interleave ----
        int rb = blockIdx.x - NCB;
        const float4* re4 = (const float4*)(xre + DIR_F);
        const float4* im4 = (const float4*)(xim + DIR_F);
        float4* o4 = (float4*)(out + DIR_F);
        int base = rb * PER_B + threadIdx.x;
#pragma unroll
        for (int k = 0; k < 4; k++) {
            int i = base + k * 128;
            float4 r = re4[i], m = im4[i];
            __stcs(&o4[2*i],     make_float4(r.x, m.x, r.y, m.y));
            __stcs(&o4[2*i + 1], make_float4(r.z, m.z, r.w, m.w));
        }
        return;
    }

    // ---- compute role: one even site ----
    int tid = blockIdx.x * 128 + threadIdx.x;
    int xi = tid % 12; int r = tid / 12;
    int y = r % 24; r /= 24;
    int z = r % 24; r /= 24;
    int t = r;
    int par = (t + z + y) & 1;
    int x = 2 * xi + par;                    // (t+z+y+x) even

    int tp = (t + 1) % 24;
    int zp = (z + 1) % 24, zm = (z + 23) % 24;
    int yp = (y + 1) % 24, ym = (y + 23) % 24;
    int xp = (x + 1) % 24, xm = (x + 23) % 24;

    double* outd = (double*)out;

    // scale_coeff(coeff,0.75) with the /6 staple average folded in
    float c[6];
#pragma unroll
    for (int i = 0; i < 6; i++)
        c[i] = (0.47746482927568606f / 6.0f) * atanf(coeff[i]);

    C3 f;
#pragma unroll
    for (int i = 0; i < 9; i++) f.m[i] = 0ull;

    staple_pair(f, xre, xim,                     // nu = 1 (Z)
                IDX9(0,t,zp,y,x), IDX9(0,t,zm,y,x),
                IDX9(1,t,z,y,x),  IDX9(1,tp,z,y,x),
                IDX9(1,t,zm,y,x), IDX9(1,tp,zm,y,x),
                c[0], c[1]);
    staple_pair(f, xre, xim,                     // nu = 2 (Y)
                IDX9(0,t,z,yp,x), IDX9(0,t,z,ym,x),
                IDX9(2,t,z,y,x),  IDX9(2,tp,z,y,x),
                IDX9(2,t,z,ym,x), IDX9(2,tp,z,ym,x),
                c[2], c[3]);

    // ---- nu = 3 (X), inlined: also emits the odd-partner dir0 copy ----
    // Partner site is x^1 = xp (par==0) or xm (par==1); its U0 matrix is the
    // staple operand we load anyway -> predicated evict-first store.
    {
        C3 A, B, C, T1, T2;
        int b0p = IDX9(0,t,z,y,xp), b0m = IDX9(0,t,z,y,xm);
        mload(A, xre, xim, b0p);        // U0(s+x)
        if (par == 0) {
#pragma unroll
            for (int i = 0; i < 9; i++)
                __stcs(&outd[b0p + i], __longlong_as_double((long long)A.m[i]));
        }
        mload(B, xre, xim, IDX9(3,tp,z,y,x));   // x3(s+t)
        cmul<1>(T1, A, B);
        mload(C, xre, xim, IDX9(3,t,z,y,x));    // x3(s)
        cmul<0>(T2, C, T1);
        macc(f, T2, c[4]);

        mload(A, xre, xim, IDX9(3,t,z,y,xm));   // x3(s-x)
        mload(B, xre, xim, b0m);                // U0(s-x)
        if (par == 1) {
#pragma unroll
            for (int i = 0; i < 9; i++)
                __stcs(&outd[b0m + i], __longlong_as_double((long long)B.m[i]));
        }
        cmul<2>(T1, A, B);
        mload(C, xre, xim, IDX9(3,tp,z,y,xm));  // x3(s-x+t)
        cmul<0>(T2, T1, C);
        macc(f, T2, c[5]);
    }

    int b0 = IDX9(0, t, z, y, x);
    C3 U0; mload(U0, xre, xim, b0);

    // Z = projectTangent(f @ U0^dag) scaled by 2^-4
    C3 Mm; cmul<1>(Mm, f, U0);
    float mr[9], mi[9];
#pragma unroll
    for (int i = 0; i < 9; i++) upk(Mm.m[i], mr[i], mi[i]);
    const float s = 0.03125f;   // 0.5 * 2^-4
    float zre[9], zim[9];
#pragma unroll
    for (int rr = 0; rr < 3; rr++)
#pragma unroll
        for (int cc = 0; cc < 3; cc++) {
            zre[rr*3+cc] = s * (mr[rr*3+cc] - mr[cc*3+rr]);
            zim[rr*3+cc] = s * (mi[rr*3+cc] + mi[cc*3+rr]);
        }
    float tri = (zim[0] + zim[4] + zim[8]) * (1.0f / 3.0f);
    zim[0] -= tri; zim[4] -= tri; zim[8] -= tri;
    C3 Z;
#pragma unroll
    for (int i = 0; i < 9; i++) Z.m[i] = pk(zre[i], zim[i]);

    // Horner Taylor, 8 terms: E = I + (Z@E)/k
    const c64 one = pk(1.0f, 0.0f);
    C3 E, T1;
#pragma unroll
    for (int i = 0; i < 9; i++) E.m[i] = (i % 4 == 0) ? one : 0ull;
#pragma unroll
    for (int k = 8; k >= 1; k--) {
        cmul<0>(T1, Z, E);
        float inv = 1.0f / (float)k;
        c64 inv2 = pk(inv, inv);
#pragma unroll
        for (int i = 0; i < 9; i++)
            E.m[i] = fma2(T1.m[i], inv2, (i % 4 == 0) ? one : 0ull);
    }
    // 4 squarings
#pragma unroll
    for (int sq = 0; sq < 4; sq++) { cmul<0>(T1, E, E); E = T1; }

    // y_mu = E @ U0 (even sites: xmu_fix = 0)
    C3 Y; cmul<0>(Y, E, U0);
#pragma unroll
    for (int i = 0; i < 9; i++)
        __stcs(&outd[b0 + i], __longlong_as_double((long long)Y.m[i]));
}

extern "C" void kernel_launch(void* const* d_in, const int* in_sizes, int n_in,
                              void* d_out, int out_size) {
    const float* xre   = (const float*)d_in[0];
    const float* xim   = (const float*)d_in[1];
    const float* coeff = (const float*)d_in[2];

    stout_fused<<<NCB + NCPB, 128>>>(xre, xim, coeff, (float2*)d_out);
}

// round 15
// speedup vs baseline: 1.0670x; 1.0035x over previous
#include <cuda_runtime.h>

// StoutSmearSlice: 24^4 lattice, 4 dirs, 3x3 complex links (separate re/im fp32).
// MU=0, update EVEN parity sites of dir 0; everything else is a copy.
//
// Round 15 = R14 (64.2us) + copy-work absorption into compute threads:
// each compute thread copies 4 dirs1-3 chunk indices (the first 1296 copy
// blocks' worth), with loads placed right before the matexp Taylor loop (pure
// FMA, no loads -> absorbs the DRAM round trip). Copy role shrinks 4374->3078
// blocks; wave-1 (compute-only) DRAM idle time is filled with copy traffic.

#define IDX9(d,t,z,y,x) ((((((d)*24+(t))*24+(z))*24+(y))*24+(x))*9)

static const int NSITE  = 24 * 24 * 24 * 12;          // even sites = 165888
static const int NCB    = NSITE / 128;                // 1296 compute blocks
static const int DIR_F  = 24 * 24 * 24 * 24 * 9;      // floats per direction
static const int COPY4  = 3 * DIR_F / 4;              // float4s in dirs 1..3
static const int PER_B  = 128 * 4;                    // float4 indices per chunk
static const int NCPB   = COPY4 / PER_B;              // 4374 total copy chunks
// compute blocks absorb chunks [0, NCB); dedicated copy blocks do the rest
static const int NCOPYB = NCPB - NCB;                 // 3078 copy blocks

typedef unsigned long long c64;   // packed {lo=re, hi=im} fp32 pair

__device__ __forceinline__ c64 pk(float lo, float hi) {
    c64 r; asm("mov.b64 %0,{%1,%2};" : "=l"(r) : "f"(lo), "f"(hi)); return r;
}
__device__ __forceinline__ void upk(c64 v, float &lo, float &hi) {
    asm("mov.b64 {%0,%1},%2;" : "=f"(lo), "=f"(hi) : "l"(v));
}
__device__ __forceinline__ c64 fma2(c64 a, c64 b, c64 c) {
    c64 d; asm("fma.rn.f32x2 %0,%1,%2,%3;" : "=l"(d) : "l"(a), "l"(b), "l"(c));
    return d;
}
__device__ __forceinline__ c64 mul2(c64 a, c64 b) {
    c64 d; asm("mul.rn.f32x2 %0,%1,%2;" : "=l"(d) : "l"(a), "l"(b)); return d;
}

struct C3 { c64 m[9]; };

// Windowed load: base b is 4B-aligned; a = b&~1 is 8B-aligned and [a, a+10)
// covers elements [b, b+9). 5 LDG.64 per array + select.
__device__ __forceinline__ void mload(C3 &A, const float* __restrict__ re,
                                      const float* __restrict__ im, int b) {
    int a = b & ~1;
    bool p = (b & 1) != 0;
    const float2* r2 = (const float2*)(re + a);
    const float2* i2 = (const float2*)(im + a);
    float fr[10], fi[10];
#pragma unroll
    for (int j = 0; j < 5; j++) {
        float2 vr = r2[j], vi = i2[j];
        fr[2*j] = vr.x; fr[2*j+1] = vr.y;
        fi[2*j] = vi.x; fi[2*j+1] = vi.y;
    }
#pragma unroll
    for (int i = 0; i < 9; i++)
        A.m[i] = pk(p ? fr[i+1] : fr[i], p ? fi[i+1] : fi[i]);
}

// MODE: 0 = A@B, 1 = A@B^dag, 2 = A^dag@B
template <int MODE>
__device__ __forceinline__ void cmul(C3 &C, const C3 &A, const C3 &B) {
#pragma unroll
    for (int r = 0; r < 3; r++) {
        float ar[3], ai[3];
#pragma unroll
        for (int k = 0; k < 3; k++)
            upk(A.m[MODE == 2 ? k * 3 + r : r * 3 + k], ar[k], ai[k]);
        c64 arr[3], aii[3];
#pragma unroll
        for (int k = 0; k < 3; k++) { arr[k] = pk(ar[k], ar[k]); aii[k] = pk(ai[k], ai[k]); }
#pragma unroll
        for (int c = 0; c < 3; c++) {
            c64 b0 = B.m[MODE == 1 ? c * 3 + 0 : 0 * 3 + c];
            c64 acc1 = mul2(arr[0], b0);
            c64 acc2 = mul2(aii[0], b0);
#pragma unroll
            for (int k = 1; k < 3; k++) {
                c64 b = B.m[MODE == 1 ? c * 3 + k : k * 3 + c];
                acc1 = fma2(arr[k], b, acc1);
                acc2 = fma2(aii[k], b, acc2);
            }
            float x1, y1, x2, y2;
            upk(acc1, x1, y1); upk(acc2, x2, y2);
            float cr, ci;
            if (MODE == 0)      { cr = x1 - y2; ci = y1 + x2; }
            else if (MODE == 1) { cr = x1 + y2; ci = x2 - y1; }
            else                { cr = x1 + y2; ci = y1 - x2; }
            C.m[r * 3 + c] = pk(cr, ci);
        }
    }
}

__device__ __forceinline__ void macc(C3 &F, const C3 &T, float c) {
    c64 cc = pk(c, c);
#pragma unroll
    for (int i = 0; i < 9; i++) F.m[i] = fma2(cc, T.m[i], F.m[i]);
}

// Forward staple (cf) + backward staple (cb) for one nu direction.
__device__ __forceinline__ void staple_pair(C3 &f,
        const float* __restrict__ xre, const float* __restrict__ xim,
        int b0p, int b0m, int bns, int bnsmu, int bnm, int bnmmu,
        float cf, float cb) {
    C3 A, B, C, T1, T2;
    mload(A, xre, xim, b0p);        // U0(s+nu)
    mload(B, xre, xim, bnsmu);      // Unu(s+mu)
    cmul<1>(T1, A, B);              // U0(s+nu) @ Unu(s+mu)^dag
    mload(C, xre, xim, bns);        // Unu(s)
    cmul<0>(T2, C, T1);
    macc(f, T2, cf);

    mload(A, xre, xim, bnm);        // Unu(s-nu)
    mload(B, xre, xim, b0m);        // U0(s-nu)
    cmul<2>(T1, A, B);              // Unu(s-nu)^dag @ U0(s-nu)
    mload(C, xre, xim, bnmmu);      // Unu(s-nu+mu)
    cmul<0>(T2, T1, C);
    macc(f, T2, cb);
}

__global__ __launch_bounds__(128) void stout_fused(
        const float* __restrict__ xre,
        const float* __restrict__ xim,
        const float* __restrict__ coeff,
        float2* __restrict__ out) {
    const float4* re4 = (const float4*)(xre + DIR_F);
    const float4* im4 = (const float4*)(xim + DIR_F);
    float4* o4 = (float4*)(out + DIR_F);

    if (blockIdx.x >= NCB) {
        // ---- copy role: dirs 1..3 chunks [NCB, NCPB) ----
        int base = (blockIdx.x - NCB + NCB) * PER_B + threadIdx.x;  // chunk id = blockIdx.x
#pragma unroll
        for (int k = 0; k < 4; k++) {
            int i = base + k * 128;
            float4 r = re4[i], m = im4[i];
            __stcs(&o4[2*i],     make_float4(r.x, m.x, r.y, m.y));
            __stcs(&o4[2*i + 1], make_float4(r.z, m.z, r.w, m.w));
        }
        return;
    }

    // ---- compute role: one even site (+ absorbed copy chunk blockIdx.x) ----
    int tid = blockIdx.x * 128 + threadIdx.x;
    int xi = tid % 12; int r = tid / 12;
    int y = r % 24; r /= 24;
    int z = r % 24; r /= 24;
    int t = r;
    int par = (t + z + y) & 1;
    int x = 2 * xi + par;                    // (t+z+y+x) even

    int tp = (t + 1) % 24;
    int zp = (z + 1) % 24, zm = (z + 23) % 24;
    int yp = (y + 1) % 24, ym = (y + 23) % 24;
    int xp = (x + 1) % 24, xm = (x + 23) % 24;

    double* outd = (double*)out;

    // scale_coeff(coeff,0.75) with the /6 staple average folded in
    float c[6];
#pragma unroll
    for (int i = 0; i < 6; i++)
        c[i] = (0.47746482927568606f / 6.0f) * atanf(coeff[i]);

    C3 f;
#pragma unroll
    for (int i = 0; i < 9; i++) f.m[i] = 0ull;

    staple_pair(f, xre, xim,                     // nu = 1 (Z)
                IDX9(0,t,zp,y,x), IDX9(0,t,zm,y,x),
                IDX9(1,t,z,y,x),  IDX9(1,tp,z,y,x),
                IDX9(1,t,zm,y,x), IDX9(1,tp,zm,y,x),
                c[0], c[1]);
    staple_pair(f, xre, xim,                     // nu = 2 (Y)
                IDX9(0,t,z,yp,x), IDX9(0,t,z,ym,x),
                IDX9(2,t,z,y,x),  IDX9(2,tp,z,y,x),
                IDX9(2,t,z,ym,x), IDX9(2,tp,z,ym,x),
                c[2], c[3]);

    // ---- nu = 3 (X), inlined: also emits the odd-partner dir0 copy ----
    {
        C3 A, B, C, T1, T2;
        int b0p = IDX9(0,t,z,y,xp), b0m = IDX9(0,t,z,y,xm);
        mload(A, xre, xim, b0p);        // U0(s+x)
        if (par == 0) {
#pragma unroll
            for (int i = 0; i < 9; i++)
                __stcs(&outd[b0p + i], __longlong_as_double((long long)A.m[i]));
        }
        mload(B, xre, xim, IDX9(3,tp,z,y,x));   // x3(s+t)
        cmul<1>(T1, A, B);
        mload(C, xre, xim, IDX9(3,t,z,y,x));    // x3(s)
        cmul<0>(T2, C, T1);
        macc(f, T2, c[4]);

        mload(A, xre, xim, IDX9(3,t,z,y,xm));   // x3(s-x)
        mload(B, xre, xim, b0m);                // U0(s-x)
        if (par == 1) {
#pragma unroll
            for (int i = 0; i < 9; i++)
                __stcs(&outd[b0m + i], __longlong_as_double((long long)B.m[i]));
        }
        cmul<2>(T1, A, B);
        mload(C, xre, xim, IDX9(3,tp,z,y,xm));  // x3(s-x+t)
        cmul<0>(T2, T1, C);
        macc(f, T2, c[5]);
    }

    int b0 = IDX9(0, t, z, y, x);
    C3 U0; mload(U0, xre, xim, b0);

    // Z = projectTangent(f @ U0^dag) scaled by 2^-4
    C3 Mm; cmul<1>(Mm, f, U0);
    float mr[9], mi[9];
#pragma unroll
    for (int i = 0; i < 9; i++) upk(Mm.m[i], mr[i], mi[i]);
    const float s = 0.03125f;   // 0.5 * 2^-4
    float zre[9], zim[9];
#pragma unroll
    for (int rr = 0; rr < 3; rr++)
#pragma unroll
        for (int cc = 0; cc < 3; cc++) {
            zre[rr*3+cc] = s * (mr[rr*3+cc] - mr[cc*3+rr]);
            zim[rr*3+cc] = s * (mi[rr*3+cc] + mi[cc*3+rr]);
        }
    float tri = (zim[0] + zim[4] + zim[8]) * (1.0f / 3.0f);
    zim[0] -= tri; zim[4] -= tri; zim[8] -= tri;
    C3 Z;
#pragma unroll
    for (int i = 0; i < 9; i++) Z.m[i] = pk(zre[i], zim[i]);

    // ---- absorbed copy chunk (chunk id = blockIdx.x): loads issue here, the
    // following matexp (pure FMA, no loads) absorbs the DRAM round trip ----
    {
        int base = blockIdx.x * PER_B + threadIdx.x;
#pragma unroll
        for (int k = 0; k < 4; k++) {
            int i = base + k * 128;
            float4 rr = re4[i], m = im4[i];
            __stcs(&o4[2*i],     make_float4(rr.x, m.x, rr.y, m.y));
            __stcs(&o4[2*i + 1], make_float4(rr.z, m.z, rr.w, m.w));
        }
    }

    // Horner Taylor, 8 terms: E = I + (Z@E)/k
    const c64 one = pk(1.0f, 0.0f);
    C3 E, T1;
#pragma unroll
    for (int i = 0; i < 9; i++) E.m[i] = (i % 4 == 0) ? one : 0ull;
#pragma unroll
    for (int k = 8; k >= 1; k--) {
        cmul<0>(T1, Z, E);
        float inv = 1.0f / (float)k;
        c64 inv2 = pk(inv, inv);
#pragma unroll
        for (int i = 0; i < 9; i++)
            E.m[i] = fma2(T1.m[i], inv2, (i % 4 == 0) ? one : 0ull);
    }
    // 4 squarings
#pragma unroll
    for (int sq = 0; sq < 4; sq++) { cmul<0>(T1, E, E); E = T1; }

    // y_mu = E @ U0 (even sites: xmu_fix = 0)
    C3 Y; cmul<0>(Y, E, U0);
#pragma unroll
    for (int i = 0; i < 9; i++)
        __stcs(&outd[b0 + i], __longlong_as_double((long long)Y.m[i]));
}

extern "C" void kernel_launch(void* const* d_in, const int* in_sizes, int n_in,
                              void* d_out, int out_size) {
    const float* xre   = (const float*)d_in[0];
    const float* xim   = (const float*)d_in[1];
    const float* coeff = (const float*)d_in[2];

    stout_fused<<<NCB + NCOPYB, 128>>>(xre, xim, coeff, (float2*)d_out);
}